// round 9
// baseline (speedup 1.0000x reference)
#include <cuda_runtime.h>
#include <math.h>

#define HIDC 128
#define NMAX 100000
#define EMAX 3200000
#define SCAN_BS 1024
#define MAX_BLKS ((NMAX + SCAN_BS - 1) / SCAN_BS)   // 98

// ---------------- scratch (no allocation allowed) ----------------
__device__ __align__(16) float g_bufA[(size_t)NMAX * HIDC];   // 51.2 MB
__device__ __align__(16) float g_bufB[(size_t)NMAX * HIDC];   // 51.2 MB
__device__ int   g_cnt[NMAX];
__device__ int   g_rowptr[NMAX + 1];
__device__ int   g_cursor[NMAX];
__device__ float g_dinv[NMAX];
__device__ int   g_srccsr[EMAX];                // 12.8 MB CSR (by dst) of src ids
__device__ int   g_is64;                        // edge_index dtype flag
__device__ int   g_blk[MAX_BLKS];               // per-block scan totals
__device__ int   g_blkoff[MAX_BLKS];            // exclusive scan of block totals

// ---------------- dtype detection ----------------
// int64 little-endian with values < 2^31 => every odd 32-bit word of the src
// half is zero. int32 => those words are random node ids. Sample 1024 words.
__global__ void detect_k(const unsigned int* __restrict__ w, int E) {
    __shared__ int found;
    if (threadIdx.x == 0) found = 0;
    __syncthreads();
    unsigned stride = (unsigned)E / 1024u;
    if (stride == 0) stride = 1;
    #pragma unroll
    for (int i = 0; i < 4; i++) {
        unsigned q = ((unsigned)threadIdx.x * 4u + i) * stride;
        if (q < (unsigned)E) {
            if (w[2u * q + 1u] != 0u) found = 1;
        }
    }
    __syncthreads();
    if (threadIdx.x == 0) g_is64 = found ? 0 : 1;
}

// which: 0 = src, 1 = dst. Works for both int32 and int64 storage.
__device__ __forceinline__ int load_idx(const int* __restrict__ w, int E, int e, int which) {
    size_t elem = (size_t)which * E + e;
    return g_is64 ? w[2 * elem] : w[elem];
}

// ---------------- setup kernels ----------------
__global__ void zero_cnt_k(int N) {
    int i = blockIdx.x * blockDim.x + threadIdx.x;
    if (i < N) g_cnt[i] = 0;
}

__global__ void count_k(const int* __restrict__ ew, int E, int N) {
    int e = blockIdx.x * blockDim.x + threadIdx.x;
    if (e < E) {
        int d = load_idx(ew, E, e, 1);
        if ((unsigned)d < (unsigned)N) atomicAdd(&g_cnt[d], 1);
    }
}

// ---------------- chip-wide 3-phase scan ----------------
// Phase 1: per-block inclusive scan of 1024 counters.
// Writes provisional inclusive scan into g_rowptr[i+1]; block total into g_blk.
__global__ void scan1_k(int N) {
    __shared__ int sh[2][SCAN_BS];
    int tid = threadIdx.x;
    int i = blockIdx.x * SCAN_BS + tid;
    int v = (i < N) ? g_cnt[i] : 0;
    sh[0][tid] = v;
    __syncthreads();
    int pin = 0;
    #pragma unroll
    for (int off = 1; off < SCAN_BS; off <<= 1) {
        int t = sh[pin][tid] + ((tid >= off) ? sh[pin][tid - off] : 0);
        sh[pin ^ 1][tid] = t;
        pin ^= 1;
        __syncthreads();
    }
    int incl = sh[pin][tid];
    if (i < N) g_rowptr[i + 1] = incl;
    if (tid == SCAN_BS - 1) g_blk[blockIdx.x] = incl;
}

// Phase 2: one block, exclusive scan of block totals (nblk <= 128).
__global__ void scan2_k(int nblk) {
    __shared__ int sh[2][128];
    int tid = threadIdx.x;
    int v = (tid < nblk) ? g_blk[tid] : 0;
    sh[0][tid] = v;
    __syncthreads();
    int pin = 0;
    #pragma unroll
    for (int off = 1; off < 128; off <<= 1) {
        int t = sh[pin][tid] + ((tid >= off) ? sh[pin][tid - off] : 0);
        sh[pin ^ 1][tid] = t;
        pin ^= 1;
        __syncthreads();
    }
    if (tid < nblk) g_blkoff[tid] = sh[pin][tid] - v;   // exclusive
}

// Phase 3: finalize rowptr, fuse cursor/dinv init.
__global__ void scan3_k(int N) {
    int i = blockIdx.x * blockDim.x + threadIdx.x;
    if (i == 0) g_rowptr[0] = 0;
    if (i < N) {
        int incl = g_rowptr[i + 1] + g_blkoff[i >> 10];
        g_rowptr[i + 1] = incl;
        int c = g_cnt[i];
        g_cursor[i] = incl - c;                 // row start
        g_dinv[i] = rsqrtf((float)c + 1.0f);    // degree incl. self-loop
    }
}

__global__ void fill_k(const int* __restrict__ ew, int E, int N) {
    int e = blockIdx.x * blockDim.x + threadIdx.x;
    if (e < E) {
        int d = load_idx(ew, E, e, 1);
        int s = load_idx(ew, E, e, 0);
        if ((unsigned)d < (unsigned)N && (unsigned)s < (unsigned)N) {
            int pos = atomicAdd(&g_cursor[d], 1);
            g_srccsr[pos] = s;
        }
    }
}

// ---------------- fp32 GEMM: C[M,128] = A[M,128] @ W[128,128], fused epilogue ----------------
__global__ __launch_bounds__(256, 2)
void gemm_k128(const float* __restrict__ Aext, int a_sel,
               const float* __restrict__ W,
               const float* __restrict__ bias, int has_bias,
               int relu_f, int rowscale_f, int c_sel, int M)
{
    __shared__ __align__(16) float As[16][132];  // [k][m], padded
    __shared__ __align__(16) float Ws[16][128];  // [k][n]
    const float* A = a_sel ? g_bufA : Aext;
    float* C = c_sel ? g_bufB : g_bufA;

    int tid = threadIdx.x;
    int tx = tid & 15, ty = tid >> 4;     // 16x16 thread grid, 8x8 micro-tile
    int blockRow = blockIdx.x * 128;

    float acc[8][8];
    #pragma unroll
    for (int i = 0; i < 8; i++)
        #pragma unroll
        for (int j = 0; j < 8; j++) acc[i][j] = 0.0f;

    for (int k0 = 0; k0 < 128; k0 += 16) {
        #pragma unroll
        for (int it = 0; it < 2; it++) {
            int lin = tid + it * 256;      // 0..511
            int r = lin >> 2;              // 0..127
            int c4 = lin & 3;              // 0..3
            int grow = blockRow + r;
            float4 v = make_float4(0.f, 0.f, 0.f, 0.f);
            if (grow < M) v = *(const float4*)(A + (size_t)grow * 128 + k0 + c4 * 4);
            As[c4 * 4 + 0][r] = v.x;
            As[c4 * 4 + 1][r] = v.y;
            As[c4 * 4 + 2][r] = v.z;
            As[c4 * 4 + 3][r] = v.w;
        }
        #pragma unroll
        for (int it = 0; it < 2; it++) {
            int lin = tid + it * 256;
            int kr = lin >> 5;             // 0..15
            int c4 = lin & 31;             // 0..31
            *(float4*)&Ws[kr][c4 * 4] =
                *(const float4*)(W + (size_t)(k0 + kr) * 128 + c4 * 4);
        }
        __syncthreads();
        #pragma unroll
        for (int k = 0; k < 16; k++) {
            float a[8], b[8];
            *(float4*)&a[0] = *(const float4*)&As[k][ty * 8];
            *(float4*)&a[4] = *(const float4*)&As[k][ty * 8 + 4];
            *(float4*)&b[0] = *(const float4*)&Ws[k][tx * 8];
            *(float4*)&b[4] = *(const float4*)&Ws[k][tx * 8 + 4];
            #pragma unroll
            for (int i = 0; i < 8; i++)
                #pragma unroll
                for (int j = 0; j < 8; j++)
                    acc[i][j] = fmaf(a[i], b[j], acc[i][j]);
        }
        __syncthreads();
    }

    #pragma unroll
    for (int i = 0; i < 8; i++) {
        int grow = blockRow + ty * 8 + i;
        if (grow >= M) continue;
        float rs = rowscale_f ? g_dinv[grow] : 1.0f;
        float o[8];
        #pragma unroll
        for (int j = 0; j < 8; j++) o[j] = acc[i][j] * rs;
        if (has_bias) {
            #pragma unroll
            for (int j = 0; j < 8; j++) o[j] += bias[tx * 8 + j];
        }
        if (relu_f) {
            #pragma unroll
            for (int j = 0; j < 8; j++) o[j] = fmaxf(o[j], 0.0f);
        }
        *(float4*)(C + (size_t)grow * 128 + tx * 8)     = *(float4*)&o[0];
        *(float4*)(C + (size_t)grow * 128 + tx * 8 + 4) = *(float4*)&o[4];
    }
}

// ---------------- pull aggregation: one warp per node ----------------
__global__ __launch_bounds__(256)
void agg_k(const float* __restrict__ gcnb, int M)
{
    int warp = (blockIdx.x * 256 + threadIdx.x) >> 5;
    int lane = threadIdx.x & 31;
    if (warp >= M) return;
    const float4* __restrict__ hs = (const float4*)g_bufB;

    float4 s0 = hs[(size_t)warp * 32 + lane];   // self loop
    float4 s1 = make_float4(0.f, 0.f, 0.f, 0.f);
    float4 s2 = s1, s3 = s1;

    int e = g_rowptr[warp];
    int end = g_rowptr[warp + 1];
    for (; e + 4 <= end; e += 4) {
        int i0 = g_srccsr[e + 0];
        int i1 = g_srccsr[e + 1];
        int i2 = g_srccsr[e + 2];
        int i3 = g_srccsr[e + 3];
        float4 v0 = hs[(size_t)i0 * 32 + lane];
        float4 v1 = hs[(size_t)i1 * 32 + lane];
        float4 v2 = hs[(size_t)i2 * 32 + lane];
        float4 v3 = hs[(size_t)i3 * 32 + lane];
        s0.x += v0.x; s0.y += v0.y; s0.z += v0.z; s0.w += v0.w;
        s1.x += v1.x; s1.y += v1.y; s1.z += v1.z; s1.w += v1.w;
        s2.x += v2.x; s2.y += v2.y; s2.z += v2.z; s2.w += v2.w;
        s3.x += v3.x; s3.y += v3.y; s3.z += v3.z; s3.w += v3.w;
    }
    for (; e < end; e++) {
        int i = g_srccsr[e];
        float4 v = hs[(size_t)i * 32 + lane];
        s0.x += v.x; s0.y += v.y; s0.z += v.z; s0.w += v.w;
    }

    float di = g_dinv[warp];
    float4 b = ((const float4*)gcnb)[lane];
    float4 o;
    o.x = fmaxf(fmaf(di, s0.x + s1.x + s2.x + s3.x, b.x), 0.0f);
    o.y = fmaxf(fmaf(di, s0.y + s1.y + s2.y + s3.y, b.y), 0.0f);
    o.z = fmaxf(fmaf(di, s0.z + s1.z + s2.z + s3.z, b.z), 0.0f);
    o.w = fmaxf(fmaf(di, s0.w + s1.w + s2.w + s3.w, b.w), 0.0f);
    ((float4*)g_bufA)[(size_t)warp * 32 + lane] = o;
}

// ---------------- lin2 + log_softmax fused: one warp per row ----------------
__global__ __launch_bounds__(256)
void lin2_softmax_k(const float* __restrict__ W2,   // [128,40]
                    const float* __restrict__ b2,   // [40]
                    float* __restrict__ out, int M)
{
    __shared__ float Ws[40][132];   // Ws[c][k] = W2[k*40+c]
    __shared__ float sb2[40];
    int tid = threadIdx.x;
    for (int i = tid; i < 40 * 128; i += 256) {
        int k = i / 40, c = i % 40;
        Ws[c][k] = W2[i];
    }
    if (tid < 40) sb2[tid] = b2[tid];
    __syncthreads();

    int lane = tid & 31, wid = tid >> 5;
    for (int row = blockIdx.x * 8 + wid; row < M; row += gridDim.x * 8) {
        const float* h = g_bufA + (size_t)row * 128;
        float a0 = h[lane];
        float a1 = h[lane + 32];
        float a2 = h[lane + 64];
        float a3 = h[lane + 96];

        float m = -1e30f;
        float v0 = 0.0f, v1 = 0.0f;   // logits for cols lane and lane+32
        #pragma unroll 8
        for (int c = 0; c < 40; c++) {
            float p = a0 * Ws[c][lane] + a1 * Ws[c][lane + 32]
                    + a2 * Ws[c][lane + 64] + a3 * Ws[c][lane + 96];
            #pragma unroll
            for (int off = 16; off > 0; off >>= 1)
                p += __shfl_xor_sync(0xffffffffu, p, off);
            p += sb2[c];
            if (c == lane) v0 = p;
            if (c == lane + 32) v1 = p;
            m = fmaxf(m, p);
        }
        float se = expf(v0 - m) + ((lane < 8) ? expf(v1 - m) : 0.0f);
        #pragma unroll
        for (int off = 16; off > 0; off >>= 1)
            se += __shfl_xor_sync(0xffffffffu, se, off);
        float lse = m + logf(se);
        out[(size_t)row * 40 + lane] = v0 - lse;
        if (lane < 8) out[(size_t)row * 40 + 32 + lane] = v1 - lse;
    }
}

// ---------------- launch ----------------
extern "C" void kernel_launch(void* const* d_in, const int* in_sizes, int n_in,
                              void* d_out, int out_size)
{
    const float* x  = (const float*)d_in[0];
    const int*   ew = (const int*)d_in[1];       // edge_index words (int32 or int64 storage)
    const float* w1 = (const float*)d_in[2];
    const float* b1 = (const float*)d_in[3];
    const float* gw = (const float*)d_in[4];     // [3,128,128]
    const float* gb = (const float*)d_in[5];     // [3,128]
    const float* w2 = (const float*)d_in[6];     // [128,40]
    const float* b2 = (const float*)d_in[7];     // [40]
    float* out = (float*)d_out;

    int N = in_sizes[0] / HIDC;
    int E = in_sizes[1] / 2;

    int nb_n = (N + 255) / 256;
    int nb_e = (E + 255) / 256;
    int nblk_scan = (N + SCAN_BS - 1) / SCAN_BS;
    int gemm_blocks = (N + 127) / 128;
    int warp_blocks = (N + 7) / 8;

    // detect int32 vs int64 edge_index storage (device-side flag)
    detect_k<<<1, 256>>>((const unsigned int*)ew, E);

    // CSR-by-dst build + symmetric-norm dinv (chip-wide scan)
    zero_cnt_k<<<nb_n, 256>>>(N);
    count_k<<<nb_e, 256>>>(ew, E, N);
    scan1_k<<<nblk_scan, SCAN_BS>>>(N);
    scan2_k<<<1, 128>>>(nblk_scan);
    scan3_k<<<nb_n, 256>>>(N);
    fill_k<<<nb_e, 256>>>(ew, E, N);

    // lin1: bufA = relu(x @ w1 + b1)
    gemm_k128<<<gemm_blocks, 256>>>(x, 0, w1, b1, /*has_bias*/1, /*relu*/1,
                                    /*rowscale*/0, /*c_sel*/0, N);
    // 3 GCN layers
    for (int k = 0; k < 3; k++) {
        gemm_k128<<<gemm_blocks, 256>>>(nullptr, 1, gw + (size_t)k * 128 * 128,
                                        nullptr, 0, 0, /*rowscale*/1, /*c_sel*/1, N);
        agg_k<<<warp_blocks, 256>>>(gb + (size_t)k * 128, N);
    }
    // logits + log_softmax
    lin2_softmax_k<<<warp_blocks, 256>>>(w2, b2, out, N);
}

// round 16
// speedup vs baseline: 1.5262x; 1.5262x over previous
#include <cuda_runtime.h>
#include <math.h>
#include <stdint.h>

#define HIDC 128
#define NMAX 100000
#define EMAX 3200000
#define SCAN_BS 1024
#define MAX_BLKS ((NMAX + SCAN_BS - 1) / SCAN_BS)   // 98
#define AST 132   // fp32 shared tile row stride (132 ≡ 4 mod 32 -> conflict-free frags)

// ---------------- scratch (no allocation allowed) ----------------
__device__ __align__(16) float g_bufA[(size_t)NMAX * HIDC];   // 51.2 MB
__device__ __align__(16) float g_bufB[(size_t)NMAX * HIDC];   // 51.2 MB
__device__ int   g_cnt[NMAX];
__device__ int   g_rowptr[NMAX + 1];
__device__ int   g_cursor[NMAX];
__device__ float g_dinv[NMAX];
__device__ int   g_srccsr[EMAX];                // 12.8 MB CSR (by dst) of src ids
__device__ int   g_is64;                        // edge_index dtype flag
__device__ int   g_blk[MAX_BLKS];
__device__ int   g_blkoff[MAX_BLKS];
// tf32-rounded split weights, transposed: [layer][n][k], stored as fp32
__device__ __align__(16) float g_wt32h[4 * 128 * 128];   // 256 KB
__device__ __align__(16) float g_wt32l[4 * 128 * 128];   // 256 KB

// ---------------- tf32 helpers ----------------
__device__ __forceinline__ uint32_t f2tf32(float v) {
    uint32_t r;
    asm("cvt.rna.tf32.f32 %0, %1;" : "=r"(r) : "f"(v));
    return r;
}
__device__ __forceinline__ void tf32split(float v, uint32_t& hi, uint32_t& lo) {
    uint32_t h = f2tf32(v);
    float res = v - __uint_as_float(h);
    lo = f2tf32(res);
    hi = h;
}
// m16n8k8 tf32 MMA, fp32 accumulate
__device__ __forceinline__ void mma_tf32(float* c, const uint32_t* a,
                                         uint32_t b0, uint32_t b1) {
    asm volatile(
        "mma.sync.aligned.m16n8k8.row.col.f32.tf32.tf32.f32 "
        "{%0,%1,%2,%3}, {%4,%5,%6,%7}, {%8,%9}, {%10,%11,%12,%13};\n"
        : "=f"(c[0]), "=f"(c[1]), "=f"(c[2]), "=f"(c[3])
        : "r"(a[0]), "r"(a[1]), "r"(a[2]), "r"(a[3]), "r"(b0), "r"(b1),
          "f"(c[0]), "f"(c[1]), "f"(c[2]), "f"(c[3]));
}

// ---------------- dtype detection ----------------
__global__ void detect_k(const unsigned int* __restrict__ w, int E) {
    __shared__ int found;
    if (threadIdx.x == 0) found = 0;
    __syncthreads();
    unsigned stride = (unsigned)E / 1024u;
    if (stride == 0) stride = 1;
    #pragma unroll
    for (int i = 0; i < 4; i++) {
        unsigned q = ((unsigned)threadIdx.x * 4u + i) * stride;
        if (q < (unsigned)E) {
            if (w[2u * q + 1u] != 0u) found = 1;
        }
    }
    __syncthreads();
    if (threadIdx.x == 0) g_is64 = found ? 0 : 1;
}
__device__ __forceinline__ int load_idx(const int* __restrict__ w, int E, int e, int which) {
    size_t elem = (size_t)which * E + e;
    return g_is64 ? w[2 * elem] : w[elem];
}

// ---------------- setup kernels ----------------
__global__ void zero_cnt_k(int N) {
    int i = blockIdx.x * blockDim.x + threadIdx.x;
    if (i < N) g_cnt[i] = 0;
}
__global__ void count_k(const int* __restrict__ ew, int E, int N) {
    int e = blockIdx.x * blockDim.x + threadIdx.x;
    if (e < E) {
        int d = load_idx(ew, E, e, 1);
        if ((unsigned)d < (unsigned)N) atomicAdd(&g_cnt[d], 1);
    }
}
__global__ void scan1_k(int N) {
    __shared__ int sh[2][SCAN_BS];
    int tid = threadIdx.x;
    int i = blockIdx.x * SCAN_BS + tid;
    int v = (i < N) ? g_cnt[i] : 0;
    sh[0][tid] = v;
    __syncthreads();
    int pin = 0;
    #pragma unroll
    for (int off = 1; off < SCAN_BS; off <<= 1) {
        int t = sh[pin][tid] + ((tid >= off) ? sh[pin][tid - off] : 0);
        sh[pin ^ 1][tid] = t;
        pin ^= 1;
        __syncthreads();
    }
    int incl = sh[pin][tid];
    if (i < N) g_rowptr[i + 1] = incl;
    if (tid == SCAN_BS - 1) g_blk[blockIdx.x] = incl;
}
__global__ void scan2_k(int nblk) {
    __shared__ int sh[2][128];
    int tid = threadIdx.x;
    int v = (tid < nblk) ? g_blk[tid] : 0;
    sh[0][tid] = v;
    __syncthreads();
    int pin = 0;
    #pragma unroll
    for (int off = 1; off < 128; off <<= 1) {
        int t = sh[pin][tid] + ((tid >= off) ? sh[pin][tid - off] : 0);
        sh[pin ^ 1][tid] = t;
        pin ^= 1;
        __syncthreads();
    }
    if (tid < nblk) g_blkoff[tid] = sh[pin][tid] - v;
}
__global__ void scan3_k(int N) {
    int i = blockIdx.x * blockDim.x + threadIdx.x;
    if (i == 0) g_rowptr[0] = 0;
    if (i < N) {
        int incl = g_rowptr[i + 1] + g_blkoff[i >> 10];
        g_rowptr[i + 1] = incl;
        int c = g_cnt[i];
        g_cursor[i] = incl - c;
        g_dinv[i] = rsqrtf((float)c + 1.0f);
    }
}
__global__ void fill_k(const int* __restrict__ ew, int E, int N) {
    int e = blockIdx.x * blockDim.x + threadIdx.x;
    if (e < E) {
        int d = load_idx(ew, E, e, 1);
        int s = load_idx(ew, E, e, 0);
        if ((unsigned)d < (unsigned)N && (unsigned)s < (unsigned)N) {
            int pos = atomicAdd(&g_cursor[d], 1);
            g_srccsr[pos] = s;
        }
    }
}

// ---------------- weight prep: tf32-split + transpose to [layer][n][k] fp32 ----------------
__global__ void prep_w_k(const float* __restrict__ w1, const float* __restrict__ gw) {
    int idx = blockIdx.x * blockDim.x + threadIdx.x;   // 0..65535
    if (idx >= 4 * 128 * 128) return;
    int l = idx >> 14;
    int r = idx & 16383;
    int k = r >> 7;            // source row (input dim)
    int n = r & 127;           // source col (output dim) — fastest => coalesced read
    const float* W = (l == 0) ? w1 : (gw + (size_t)(l - 1) * 16384);
    float v = W[k * 128 + n];
    uint32_t hi, lo;
    tf32split(v, hi, lo);
    int dsti = (l << 14) | (n << 7) | k;               // [l][n][k]
    g_wt32h[dsti] = __uint_as_float(hi);
    g_wt32l[dsti] = __uint_as_float(lo);
}

// ---------------- 3xTF32 tensor-core GEMM ----------------
// C[M,128] = A[M,128] @ W[128,128], D = Ah*Wh + Ah*Wl + Al*Wh (fp32 accum).
// Weights resolved IN-KERNEL from layer index (never pass __device__ symbols
// from host — on GB300/ATS the host shadow address is silently readable!).
__global__ __launch_bounds__(256)
void gemm_tf32(const float* __restrict__ Aext, int a_sel, int layer,
               const float* __restrict__ bias, int has_bias,
               int relu_f, int rowscale_f, int c_sel, int M)
{
    extern __shared__ __align__(16) float smf[];
    float* sA  = smf;                   // [128][AST]
    float* sWh = sA + 128 * AST;
    float* sWl = sWh + 128 * AST;

    const float* A = a_sel ? g_bufA : Aext;
    float* C = c_sel ? g_bufB : g_bufA;
    const float* Wh = g_wt32h + (size_t)layer * 16384;   // device-side resolution
    const float* Wl = g_wt32l + (size_t)layer * 16384;
    int tid = threadIdx.x, wid = tid >> 5, lane = tid & 31;
    int qr = lane >> 2, qc = lane & 3;      // groupID, threadID_in_group
    int blockRow = blockIdx.x * 128;

    // ---- stage A (raw fp32) ----
    #pragma unroll 4
    for (int it = 0; it < 16; it++) {
        int idx4 = tid + it * 256;            // 0..4095 float4s
        int r = idx4 >> 5;                    // row 0..127
        int k = (idx4 & 31) * 4;              // 0..124
        int grow = blockRow + r;
        float4 v = make_float4(0.f, 0.f, 0.f, 0.f);
        if (grow < M) v = *(const float4*)(A + (size_t)grow * 128 + k);
        *(float4*)&sA[r * AST + k] = v;
    }
    // ---- stage Wh/Wl ([n][k] fp32, contiguous in global) ----
    #pragma unroll 4
    for (int it = 0; it < 32; it++) {
        int idx = tid + it * 256;             // 0..8191 float4s
        int s = idx >> 12;                    // 0 hi, 1 lo
        int r2 = idx & 4095;
        int n = r2 >> 5;
        int kq = (r2 & 31) * 4;
        const float* src = s ? Wl : Wh;
        float4 v = *(const float4*)(src + n * 128 + kq);
        float* dst = s ? sWl : sWh;
        *(float4*)&dst[n * AST + kq] = v;
    }
    __syncthreads();

    int wrow = (wid & 3) * 32;          // warp row base within tile
    int chalf = (wid >> 2) * 64;        // warp col base

    float acc[2][8][4];
    #pragma unroll
    for (int rt = 0; rt < 2; rt++)
        #pragma unroll
        for (int j = 0; j < 8; j++)
            #pragma unroll
            for (int q = 0; q < 4; q++) acc[rt][j][q] = 0.0f;

    #pragma unroll
    for (int kk = 0; kk < 16; kk++) {
        int k0 = kk * 8;
        // A frags (m16n8k8 tf32): a0 (row g, k qc); a1 (g+8, qc); a2 (g, qc+4); a3 (g+8, qc+4)
        uint32_t ah[2][4], al[2][4];
        #pragma unroll
        for (int rt = 0; rt < 2; rt++) {
            int r0 = wrow + rt * 16 + qr;
            int b0i = r0 * AST + k0 + qc;
            tf32split(sA[b0i],               ah[rt][0], al[rt][0]);
            tf32split(sA[b0i + 8 * AST],     ah[rt][1], al[rt][1]);
            tf32split(sA[b0i + 4],           ah[rt][2], al[rt][2]);
            tf32split(sA[b0i + 8 * AST + 4], ah[rt][3], al[rt][3]);
        }
        #pragma unroll
        for (int j = 0; j < 8; j++) {
            // B frag: b0 = W[k qc][n g], b1 = W[k qc+4][n g]; sW stored [n][k]
            int nb = (chalf + j * 8 + qr) * AST + k0 + qc;
            uint32_t bh0 = __float_as_uint(sWh[nb]);
            uint32_t bh1 = __float_as_uint(sWh[nb + 4]);
            uint32_t bl0 = __float_as_uint(sWl[nb]);
            uint32_t bl1 = __float_as_uint(sWl[nb + 4]);
            #pragma unroll
            for (int rt = 0; rt < 2; rt++) {
                mma_tf32(acc[rt][j], ah[rt], bh0, bh1);
                mma_tf32(acc[rt][j], ah[rt], bl0, bl1);
                mma_tf32(acc[rt][j], al[rt], bh0, bh1);
            }
        }
    }

    // ---- epilogue: c0,c1 = row g, cols 2qc,2qc+1; c2,c3 = row g+8 ----
    #pragma unroll
    for (int rt = 0; rt < 2; rt++) {
        int r1 = blockRow + wrow + rt * 16 + qr;
        int r2 = r1 + 8;
        float rs1 = 1.0f, rs2 = 1.0f;
        if (rowscale_f) {
            if (r1 < M) rs1 = g_dinv[r1];
            if (r2 < M) rs2 = g_dinv[r2];
        }
        #pragma unroll
        for (int j = 0; j < 8; j++) {
            int col = chalf + j * 8 + qc * 2;
            float bx = 0.f, by = 0.f;
            if (has_bias) { bx = bias[col]; by = bias[col + 1]; }
            float o0 = acc[rt][j][0] * rs1 + bx;
            float o1 = acc[rt][j][1] * rs1 + by;
            float o2 = acc[rt][j][2] * rs2 + bx;
            float o3 = acc[rt][j][3] * rs2 + by;
            if (relu_f) {
                o0 = fmaxf(o0, 0.f); o1 = fmaxf(o1, 0.f);
                o2 = fmaxf(o2, 0.f); o3 = fmaxf(o3, 0.f);
            }
            if (r1 < M) *(float2*)(C + (size_t)r1 * 128 + col) = make_float2(o0, o1);
            if (r2 < M) *(float2*)(C + (size_t)r2 * 128 + col) = make_float2(o2, o3);
        }
    }
}

// ---------------- pull aggregation: one warp per node ----------------
__global__ __launch_bounds__(256)
void agg_k(const float* __restrict__ gcnb, int M)
{
    int warp = (blockIdx.x * 256 + threadIdx.x) >> 5;
    int lane = threadIdx.x & 31;
    if (warp >= M) return;
    const float4* __restrict__ hs = (const float4*)g_bufB;

    float4 s0 = hs[(size_t)warp * 32 + lane];   // self loop
    float4 s1 = make_float4(0.f, 0.f, 0.f, 0.f);
    float4 s2 = s1, s3 = s1;

    int e = g_rowptr[warp];
    int end = g_rowptr[warp + 1];
    for (; e + 4 <= end; e += 4) {
        int i0 = g_srccsr[e + 0];
        int i1 = g_srccsr[e + 1];
        int i2 = g_srccsr[e + 2];
        int i3 = g_srccsr[e + 3];
        float4 v0 = hs[(size_t)i0 * 32 + lane];
        float4 v1 = hs[(size_t)i1 * 32 + lane];
        float4 v2 = hs[(size_t)i2 * 32 + lane];
        float4 v3 = hs[(size_t)i3 * 32 + lane];
        s0.x += v0.x; s0.y += v0.y; s0.z += v0.z; s0.w += v0.w;
        s1.x += v1.x; s1.y += v1.y; s1.z += v1.z; s1.w += v1.w;
        s2.x += v2.x; s2.y += v2.y; s2.z += v2.z; s2.w += v2.w;
        s3.x += v3.x; s3.y += v3.y; s3.z += v3.z; s3.w += v3.w;
    }
    for (; e < end; e++) {
        int i = g_srccsr[e];
        float4 v = hs[(size_t)i * 32 + lane];
        s0.x += v.x; s0.y += v.y; s0.z += v.z; s0.w += v.w;
    }

    float di = g_dinv[warp];
    float4 b = ((const float4*)gcnb)[lane];
    float4 o;
    o.x = fmaxf(fmaf(di, s0.x + s1.x + s2.x + s3.x, b.x), 0.0f);
    o.y = fmaxf(fmaf(di, s0.y + s1.y + s2.y + s3.y, b.y), 0.0f);
    o.z = fmaxf(fmaf(di, s0.z + s1.z + s2.z + s3.z, b.z), 0.0f);
    o.w = fmaxf(fmaf(di, s0.w + s1.w + s2.w + s3.w, b.w), 0.0f);
    ((float4*)g_bufA)[(size_t)warp * 32 + lane] = o;
}

// ---------------- lin2 + log_softmax fused: one warp per row ----------------
__global__ __launch_bounds__(256)
void lin2_softmax_k(const float* __restrict__ W2,
                    const float* __restrict__ b2,
                    float* __restrict__ out, int M)
{
    __shared__ float Ws[40][132];
    __shared__ float sb2[40];
    int tid = threadIdx.x;
    for (int i = tid; i < 40 * 128; i += 256) {
        int k = i / 40, c = i % 40;
        Ws[c][k] = W2[i];
    }
    if (tid < 40) sb2[tid] = b2[tid];
    __syncthreads();

    int lane = tid & 31, wid = tid >> 5;
    for (int row = blockIdx.x * 8 + wid; row < M; row += gridDim.x * 8) {
        const float* h = g_bufA + (size_t)row * 128;
        float a0 = h[lane];
        float a1 = h[lane + 32];
        float a2 = h[lane + 64];
        float a3 = h[lane + 96];

        float m = -1e30f;
        float v0 = 0.0f, v1 = 0.0f;
        #pragma unroll 8
        for (int c = 0; c < 40; c++) {
            float p = a0 * Ws[c][lane] + a1 * Ws[c][lane + 32]
                    + a2 * Ws[c][lane + 64] + a3 * Ws[c][lane + 96];
            #pragma unroll
            for (int off = 16; off > 0; off >>= 1)
                p += __shfl_xor_sync(0xffffffffu, p, off);
            p += sb2[c];
            if (c == lane) v0 = p;
            if (c == lane + 32) v1 = p;
            m = fmaxf(m, p);
        }
        float se = expf(v0 - m) + ((lane < 8) ? expf(v1 - m) : 0.0f);
        #pragma unroll
        for (int off = 16; off > 0; off >>= 1)
            se += __shfl_xor_sync(0xffffffffu, se, off);
        float lse = m + logf(se);
        out[(size_t)row * 40 + lane] = v0 - lse;
        if (lane < 8) out[(size_t)row * 40 + 32 + lane] = v1 - lse;
    }
}

// ---------------- launch ----------------
extern "C" void kernel_launch(void* const* d_in, const int* in_sizes, int n_in,
                              void* d_out, int out_size)
{
    const float* x  = (const float*)d_in[0];
    const int*   ew = (const int*)d_in[1];
    const float* w1 = (const float*)d_in[2];
    const float* b1 = (const float*)d_in[3];
    const float* gw = (const float*)d_in[4];
    const float* gb = (const float*)d_in[5];
    const float* w2 = (const float*)d_in[6];
    const float* b2 = (const float*)d_in[7];
    float* out = (float*)d_out;

    int N = in_sizes[0] / HIDC;
    int E = in_sizes[1] / 2;

    int nb_n = (N + 255) / 256;
    int nb_e = (E + 255) / 256;
    int nblk_scan = (N + SCAN_BS - 1) / SCAN_BS;
    int gemm_blocks = (N + 127) / 128;
    int warp_blocks = (N + 7) / 8;

    const int GEMM_SMEM = 3 * 128 * AST * 4;   // 202752 B
    cudaFuncSetAttribute(gemm_tf32, cudaFuncAttributeMaxDynamicSharedMemorySize, GEMM_SMEM);

    detect_k<<<1, 256>>>((const unsigned int*)ew, E);
    prep_w_k<<<256, 256>>>(w1, gw);

    zero_cnt_k<<<nb_n, 256>>>(N);
    count_k<<<nb_e, 256>>>(ew, E, N);
    scan1_k<<<nblk_scan, SCAN_BS>>>(N);
    scan2_k<<<1, 128>>>(nblk_scan);
    scan3_k<<<nb_n, 256>>>(N);
    fill_k<<<nb_e, 256>>>(ew, E, N);

    // lin1: bufA = relu(x @ w1 + b1)
    gemm_tf32<<<gemm_blocks, 256, GEMM_SMEM>>>(x, 0, /*layer*/0,
                                               b1, 1, 1, 0, 0, N);
    // 3 GCN layers
    for (int k = 0; k < 3; k++) {
        gemm_tf32<<<gemm_blocks, 256, GEMM_SMEM>>>(nullptr, 1, /*layer*/k + 1,
                                                   nullptr, 0, 0, 1, 1, N);
        agg_k<<<warp_blocks, 256>>>(gb + (size_t)k * 128, N);
    }
    lin2_softmax_k<<<warp_blocks, 256>>>(w2, b2, out, N);
}

// round 17
// speedup vs baseline: 1.7810x; 1.1670x over previous
#include <cuda_runtime.h>
#include <math.h>
#include <stdint.h>

#define HIDC 128
#define NMAX 100000
#define EMAX 3200000
#define SCAN_BS 1024
#define MAX_BLKS ((NMAX + SCAN_BS - 1) / SCAN_BS)   // 98
#define AST 132   // fp32 shared tile row stride (132 ≡ 4 mod 32 -> conflict-free frags)

// ---------------- scratch (no allocation allowed) ----------------
__device__ __align__(16) float g_bufA[(size_t)NMAX * HIDC];   // 51.2 MB
__device__ __align__(16) float g_bufB[(size_t)NMAX * HIDC];   // 51.2 MB
__device__ int   g_cnt[NMAX];
__device__ int   g_rowptr[NMAX + 1];
__device__ int   g_cursor[NMAX];
__device__ float g_dinv[NMAX];
__device__ int   g_srccsr[EMAX];                // 12.8 MB CSR (by dst) of src ids
__device__ int   g_is64;                        // edge_index dtype flag
__device__ int   g_blk[MAX_BLKS];
__device__ int   g_blkoff[MAX_BLKS];
// tf32-rounded split weights, transposed: [layer][n][k], stored as fp32
__device__ __align__(16) float g_wt32h[4 * 128 * 128];   // 256 KB
__device__ __align__(16) float g_wt32l[4 * 128 * 128];   // 256 KB
// lin2 weights, split + transposed [n][k] (n<40)
__device__ __align__(16) float g_w2h[40 * 128];
__device__ __align__(16) float g_w2l[40 * 128];

// ---------------- tf32 helpers ----------------
__device__ __forceinline__ uint32_t f2tf32(float v) {
    uint32_t r;
    asm("cvt.rna.tf32.f32 %0, %1;" : "=r"(r) : "f"(v));
    return r;
}
__device__ __forceinline__ void tf32split(float v, uint32_t& hi, uint32_t& lo) {
    uint32_t h = f2tf32(v);
    float res = v - __uint_as_float(h);
    lo = f2tf32(res);
    hi = h;
}
// m16n8k8 tf32 MMA, fp32 accumulate
__device__ __forceinline__ void mma_tf32(float* c, const uint32_t* a,
                                         uint32_t b0, uint32_t b1) {
    asm volatile(
        "mma.sync.aligned.m16n8k8.row.col.f32.tf32.tf32.f32 "
        "{%0,%1,%2,%3}, {%4,%5,%6,%7}, {%8,%9}, {%10,%11,%12,%13};\n"
        : "=f"(c[0]), "=f"(c[1]), "=f"(c[2]), "=f"(c[3])
        : "r"(a[0]), "r"(a[1]), "r"(a[2]), "r"(a[3]), "r"(b0), "r"(b1),
          "f"(c[0]), "f"(c[1]), "f"(c[2]), "f"(c[3]));
}

// ---------------- dtype detection ----------------
__global__ void detect_k(const unsigned int* __restrict__ w, int E) {
    __shared__ int found;
    if (threadIdx.x == 0) found = 0;
    __syncthreads();
    unsigned stride = (unsigned)E / 1024u;
    if (stride == 0) stride = 1;
    #pragma unroll
    for (int i = 0; i < 4; i++) {
        unsigned q = ((unsigned)threadIdx.x * 4u + i) * stride;
        if (q < (unsigned)E) {
            if (w[2u * q + 1u] != 0u) found = 1;
        }
    }
    __syncthreads();
    if (threadIdx.x == 0) g_is64 = found ? 0 : 1;
}

// ---------------- setup kernels ----------------
__global__ void zero_cnt_k(int N) {
    int i = blockIdx.x * blockDim.x + threadIdx.x;
    if (i < N) g_cnt[i] = 0;
}
// 2 edges per thread; 64-bit loads in is64 mode
__global__ void count_k(const int* __restrict__ ew, int E, int N) {
    int t = blockIdx.x * blockDim.x + threadIdx.x;
    int e0 = t * 2;
    if (e0 >= E) return;
    int d0 = -1, d1 = -1;
    if (g_is64) {
        const long long* w64 = (const long long*)ew;
        d0 = (int)w64[(size_t)E + e0];
        if (e0 + 1 < E) d1 = (int)w64[(size_t)E + e0 + 1];
    } else {
        d0 = ew[(size_t)E + e0];
        if (e0 + 1 < E) d1 = ew[(size_t)E + e0 + 1];
    }
    if ((unsigned)d0 < (unsigned)N) atomicAdd(&g_cnt[d0], 1);
    if ((unsigned)d1 < (unsigned)N) atomicAdd(&g_cnt[d1], 1);
}
__global__ void scan1_k(int N) {
    __shared__ int sh[2][SCAN_BS];
    int tid = threadIdx.x;
    int i = blockIdx.x * SCAN_BS + tid;
    int v = (i < N) ? g_cnt[i] : 0;
    sh[0][tid] = v;
    __syncthreads();
    int pin = 0;
    #pragma unroll
    for (int off = 1; off < SCAN_BS; off <<= 1) {
        int t = sh[pin][tid] + ((tid >= off) ? sh[pin][tid - off] : 0);
        sh[pin ^ 1][tid] = t;
        pin ^= 1;
        __syncthreads();
    }
    int incl = sh[pin][tid];
    if (i < N) g_rowptr[i + 1] = incl;
    if (tid == SCAN_BS - 1) g_blk[blockIdx.x] = incl;
}
__global__ void scan2_k(int nblk) {
    __shared__ int sh[2][128];
    int tid = threadIdx.x;
    int v = (tid < nblk) ? g_blk[tid] : 0;
    sh[0][tid] = v;
    __syncthreads();
    int pin = 0;
    #pragma unroll
    for (int off = 1; off < 128; off <<= 1) {
        int t = sh[pin][tid] + ((tid >= off) ? sh[pin][tid - off] : 0);
        sh[pin ^ 1][tid] = t;
        pin ^= 1;
        __syncthreads();
    }
    if (tid < nblk) g_blkoff[tid] = sh[pin][tid] - v;
}
__global__ void scan3_k(int N) {
    int i = blockIdx.x * blockDim.x + threadIdx.x;
    if (i == 0) g_rowptr[0] = 0;
    if (i < N) {
        int incl = g_rowptr[i + 1] + g_blkoff[i >> 10];
        g_rowptr[i + 1] = incl;
        int c = g_cnt[i];
        g_cursor[i] = incl - c;
        g_dinv[i] = rsqrtf((float)c + 1.0f);
    }
}
// 2 edges per thread; 64-bit loads in is64 mode
__global__ void fill_k(const int* __restrict__ ew, int E, int N) {
    int t = blockIdx.x * blockDim.x + threadIdx.x;
    int e0 = t * 2;
    if (e0 >= E) return;
    int s0 = -1, d0 = -1, s1 = -1, d1 = -1;
    if (g_is64) {
        const long long* w64 = (const long long*)ew;
        s0 = (int)w64[e0];
        d0 = (int)w64[(size_t)E + e0];
        if (e0 + 1 < E) {
            s1 = (int)w64[e0 + 1];
            d1 = (int)w64[(size_t)E + e0 + 1];
        }
    } else {
        s0 = ew[e0];
        d0 = ew[(size_t)E + e0];
        if (e0 + 1 < E) {
            s1 = ew[e0 + 1];
            d1 = ew[(size_t)E + e0 + 1];
        }
    }
    if ((unsigned)d0 < (unsigned)N && (unsigned)s0 < (unsigned)N) {
        int pos = atomicAdd(&g_cursor[d0], 1);
        g_srccsr[pos] = s0;
    }
    if ((unsigned)d1 < (unsigned)N && (unsigned)s1 < (unsigned)N) {
        int pos = atomicAdd(&g_cursor[d1], 1);
        g_srccsr[pos] = s1;
    }
}

// ---------------- weight prep: tf32-split + transpose to [layer][n][k] fp32 ----------------
__global__ void prep_w_k(const float* __restrict__ w1, const float* __restrict__ gw) {
    int idx = blockIdx.x * blockDim.x + threadIdx.x;   // 0..65535
    if (idx >= 4 * 128 * 128) return;
    int l = idx >> 14;
    int r = idx & 16383;
    int k = r >> 7;            // source row (input dim)
    int n = r & 127;           // source col (output dim) — fastest => coalesced read
    const float* W = (l == 0) ? w1 : (gw + (size_t)(l - 1) * 16384);
    float v = W[k * 128 + n];
    uint32_t hi, lo;
    tf32split(v, hi, lo);
    int dsti = (l << 14) | (n << 7) | k;               // [l][n][k]
    g_wt32h[dsti] = __uint_as_float(hi);
    g_wt32l[dsti] = __uint_as_float(lo);
}
// lin2 weights: W2 [128][40] -> [n][k] split
__global__ void prep_w2_k(const float* __restrict__ W2) {
    int idx = blockIdx.x * blockDim.x + threadIdx.x;   // 0..5119
    if (idx >= 40 * 128) return;
    int k = idx / 40;
    int n = idx % 40;          // fastest => coalesced read
    float v = W2[k * 40 + n];
    uint32_t hi, lo;
    tf32split(v, hi, lo);
    g_w2h[n * 128 + k] = __uint_as_float(hi);
    g_w2l[n * 128 + k] = __uint_as_float(lo);
}

// ---------------- 3xTF32 tensor-core GEMM (proven round 16; unchanged) ----------------
__global__ __launch_bounds__(256)
void gemm_tf32(const float* __restrict__ Aext, int a_sel, int layer,
               const float* __restrict__ bias, int has_bias,
               int relu_f, int rowscale_f, int c_sel, int M)
{
    extern __shared__ __align__(16) float smf[];
    float* sA  = smf;                   // [128][AST]
    float* sWh = sA + 128 * AST;
    float* sWl = sWh + 128 * AST;

    const float* A = a_sel ? g_bufA : Aext;
    float* C = c_sel ? g_bufB : g_bufA;
    const float* Wh = g_wt32h + (size_t)layer * 16384;   // device-side resolution
    const float* Wl = g_wt32l + (size_t)layer * 16384;
    int tid = threadIdx.x, wid = tid >> 5, lane = tid & 31;
    int qr = lane >> 2, qc = lane & 3;      // groupID, threadID_in_group
    int blockRow = blockIdx.x * 128;

    #pragma unroll 4
    for (int it = 0; it < 16; it++) {
        int idx4 = tid + it * 256;            // 0..4095 float4s
        int r = idx4 >> 5;                    // row 0..127
        int k = (idx4 & 31) * 4;              // 0..124
        int grow = blockRow + r;
        float4 v = make_float4(0.f, 0.f, 0.f, 0.f);
        if (grow < M) v = *(const float4*)(A + (size_t)grow * 128 + k);
        *(float4*)&sA[r * AST + k] = v;
    }
    #pragma unroll 4
    for (int it = 0; it < 32; it++) {
        int idx = tid + it * 256;             // 0..8191 float4s
        int s = idx >> 12;                    // 0 hi, 1 lo
        int r2 = idx & 4095;
        int n = r2 >> 5;
        int kq = (r2 & 31) * 4;
        const float* src = s ? Wl : Wh;
        float4 v = *(const float4*)(src + n * 128 + kq);
        float* dst = s ? sWl : sWh;
        *(float4*)&dst[n * AST + kq] = v;
    }
    __syncthreads();

    int wrow = (wid & 3) * 32;
    int chalf = (wid >> 2) * 64;

    float acc[2][8][4];
    #pragma unroll
    for (int rt = 0; rt < 2; rt++)
        #pragma unroll
        for (int j = 0; j < 8; j++)
            #pragma unroll
            for (int q = 0; q < 4; q++) acc[rt][j][q] = 0.0f;

    #pragma unroll
    for (int kk = 0; kk < 16; kk++) {
        int k0 = kk * 8;
        uint32_t ah[2][4], al[2][4];
        #pragma unroll
        for (int rt = 0; rt < 2; rt++) {
            int r0 = wrow + rt * 16 + qr;
            int b0i = r0 * AST + k0 + qc;
            tf32split(sA[b0i],               ah[rt][0], al[rt][0]);
            tf32split(sA[b0i + 8 * AST],     ah[rt][1], al[rt][1]);
            tf32split(sA[b0i + 4],           ah[rt][2], al[rt][2]);
            tf32split(sA[b0i + 8 * AST + 4], ah[rt][3], al[rt][3]);
        }
        #pragma unroll
        for (int j = 0; j < 8; j++) {
            int nb = (chalf + j * 8 + qr) * AST + k0 + qc;
            uint32_t bh0 = __float_as_uint(sWh[nb]);
            uint32_t bh1 = __float_as_uint(sWh[nb + 4]);
            uint32_t bl0 = __float_as_uint(sWl[nb]);
            uint32_t bl1 = __float_as_uint(sWl[nb + 4]);
            #pragma unroll
            for (int rt = 0; rt < 2; rt++) {
                mma_tf32(acc[rt][j], ah[rt], bh0, bh1);
                mma_tf32(acc[rt][j], ah[rt], bl0, bl1);
                mma_tf32(acc[rt][j], al[rt], bh0, bh1);
            }
        }
    }

    #pragma unroll
    for (int rt = 0; rt < 2; rt++) {
        int r1 = blockRow + wrow + rt * 16 + qr;
        int r2 = r1 + 8;
        float rs1 = 1.0f, rs2 = 1.0f;
        if (rowscale_f) {
            if (r1 < M) rs1 = g_dinv[r1];
            if (r2 < M) rs2 = g_dinv[r2];
        }
        #pragma unroll
        for (int j = 0; j < 8; j++) {
            int col = chalf + j * 8 + qc * 2;
            float bx = 0.f, by = 0.f;
            if (has_bias) { bx = bias[col]; by = bias[col + 1]; }
            float o0 = acc[rt][j][0] * rs1 + bx;
            float o1 = acc[rt][j][1] * rs1 + by;
            float o2 = acc[rt][j][2] * rs2 + bx;
            float o3 = acc[rt][j][3] * rs2 + by;
            if (relu_f) {
                o0 = fmaxf(o0, 0.f); o1 = fmaxf(o1, 0.f);
                o2 = fmaxf(o2, 0.f); o3 = fmaxf(o3, 0.f);
            }
            if (r1 < M) *(float2*)(C + (size_t)r1 * 128 + col) = make_float2(o0, o1);
            if (r2 < M) *(float2*)(C + (size_t)r2 * 128 + col) = make_float2(o2, o3);
        }
    }
}

// ---------------- pull aggregation: one warp per node ----------------
__global__ __launch_bounds__(256)
void agg_k(const float* __restrict__ gcnb, int M)
{
    int warp = (blockIdx.x * 256 + threadIdx.x) >> 5;
    int lane = threadIdx.x & 31;
    if (warp >= M) return;
    const float4* __restrict__ hs = (const float4*)g_bufB;

    float4 s0 = hs[(size_t)warp * 32 + lane];   // self loop
    float4 s1 = make_float4(0.f, 0.f, 0.f, 0.f);
    float4 s2 = s1, s3 = s1;

    int e = g_rowptr[warp];
    int end = g_rowptr[warp + 1];
    for (; e + 4 <= end; e += 4) {
        int i0 = g_srccsr[e + 0];
        int i1 = g_srccsr[e + 1];
        int i2 = g_srccsr[e + 2];
        int i3 = g_srccsr[e + 3];
        float4 v0 = hs[(size_t)i0 * 32 + lane];
        float4 v1 = hs[(size_t)i1 * 32 + lane];
        float4 v2 = hs[(size_t)i2 * 32 + lane];
        float4 v3 = hs[(size_t)i3 * 32 + lane];
        s0.x += v0.x; s0.y += v0.y; s0.z += v0.z; s0.w += v0.w;
        s1.x += v1.x; s1.y += v1.y; s1.z += v1.z; s1.w += v1.w;
        s2.x += v2.x; s2.y += v2.y; s2.z += v2.z; s2.w += v2.w;
        s3.x += v3.x; s3.y += v3.y; s3.z += v3.z; s3.w += v3.w;
    }
    for (; e < end; e++) {
        int i = g_srccsr[e];
        float4 v = hs[(size_t)i * 32 + lane];
        s0.x += v.x; s0.y += v.y; s0.z += v.z; s0.w += v.w;
    }

    float di = g_dinv[warp];
    float4 b = ((const float4*)gcnb)[lane];
    float4 o;
    o.x = fmaxf(fmaf(di, s0.x + s1.x + s2.x + s3.x, b.x), 0.0f);
    o.y = fmaxf(fmaf(di, s0.y + s1.y + s2.y + s3.y, b.y), 0.0f);
    o.z = fmaxf(fmaf(di, s0.z + s1.z + s2.z + s3.z, b.z), 0.0f);
    o.w = fmaxf(fmaf(di, s0.w + s1.w + s2.w + s3.w, b.w), 0.0f);
    ((float4*)g_bufA)[(size_t)warp * 32 + lane] = o;
}

// ---------------- lin2 + log_softmax via 3xTF32 MMA ----------------
// Tile: 128 rows x 40 cols. 8 warps x 16 rows. Lane(qr,qc) holds rows
// (wid*16+qr, +8), cols {8j+2qc, 8j+2qc+1}, j=0..4. Row's 40 logits live in
// the 4 quad lanes -> 2-shfl reductions for max and sum-exp.
__global__ __launch_bounds__(256)
void lin2_mma(const float* __restrict__ b2, float* __restrict__ out, int M)
{
    extern __shared__ __align__(16) float smf[];
    float* sA  = smf;                    // [128][AST]
    float* sWh = sA + 128 * AST;         // [40][AST]
    float* sWl = sWh + 40 * AST;
    float* sb2 = sWl + 40 * AST;         // [40]

    int tid = threadIdx.x, wid = tid >> 5, lane = tid & 31;
    int qr = lane >> 2, qc = lane & 3;
    int blockRow = blockIdx.x * 128;

    #pragma unroll 4
    for (int it = 0; it < 16; it++) {
        int idx4 = tid + it * 256;
        int r = idx4 >> 5;
        int k = (idx4 & 31) * 4;
        int grow = blockRow + r;
        float4 v = make_float4(0.f, 0.f, 0.f, 0.f);
        if (grow < M) v = *(const float4*)(g_bufA + (size_t)grow * 128 + k);
        *(float4*)&sA[r * AST + k] = v;
    }
    // stage W2 hi/lo: 2 x 1280 float4
    for (int it = 0; it < 10; it++) {
        int idx = tid + it * 256;            // 0..2559
        int s = idx >= 1280;
        int r2 = idx - s * 1280;
        int n = r2 >> 5;
        int kq = (r2 & 31) * 4;
        const float* src = s ? g_w2l : g_w2h;
        float4 v = *(const float4*)(src + n * 128 + kq);
        float* dst = s ? sWl : sWh;
        *(float4*)&dst[n * AST + kq] = v;
    }
    if (tid < 40) sb2[tid] = b2[tid];
    __syncthreads();

    float acc[5][4];
    #pragma unroll
    for (int j = 0; j < 5; j++)
        #pragma unroll
        for (int q = 0; q < 4; q++) acc[j][q] = 0.0f;

    #pragma unroll
    for (int kk = 0; kk < 16; kk++) {
        int k0 = kk * 8;
        uint32_t ah[4], al[4];
        int r0 = wid * 16 + qr;
        int b0i = r0 * AST + k0 + qc;
        tf32split(sA[b0i],               ah[0], al[0]);
        tf32split(sA[b0i + 8 * AST],     ah[1], al[1]);
        tf32split(sA[b0i + 4],           ah[2], al[2]);
        tf32split(sA[b0i + 8 * AST + 4], ah[3], al[3]);
        #pragma unroll
        for (int j = 0; j < 5; j++) {
            int nb = (j * 8 + qr) * AST + k0 + qc;
            uint32_t bh0 = __float_as_uint(sWh[nb]);
            uint32_t bh1 = __float_as_uint(sWh[nb + 4]);
            uint32_t bl0 = __float_as_uint(sWl[nb]);
            uint32_t bl1 = __float_as_uint(sWl[nb + 4]);
            mma_tf32(acc[j], ah, bh0, bh1);
            mma_tf32(acc[j], ah, bl0, bl1);
            mma_tf32(acc[j], al, bh0, bh1);
        }
    }

    // add bias; split rows
    float v0[5], v1[5], v2[5], v3[5];
    #pragma unroll
    for (int j = 0; j < 5; j++) {
        int col = j * 8 + qc * 2;
        float bx = sb2[col], by = sb2[col + 1];
        v0[j] = acc[j][0] + bx;  v1[j] = acc[j][1] + by;   // row r1
        v2[j] = acc[j][2] + bx;  v3[j] = acc[j][3] + by;   // row r2 = r1+8
    }
    int r1 = blockRow + wid * 16 + qr;
    int r2 = r1 + 8;

    // row r1 log_softmax (quad reduction: xor 1, xor 2 stay within quad)
    {
        float m = -1e30f;
        #pragma unroll
        for (int j = 0; j < 5; j++) m = fmaxf(m, fmaxf(v0[j], v1[j]));
        m = fmaxf(m, __shfl_xor_sync(0xffffffffu, m, 1));
        m = fmaxf(m, __shfl_xor_sync(0xffffffffu, m, 2));
        float s = 0.f;
        #pragma unroll
        for (int j = 0; j < 5; j++) s += expf(v0[j] - m) + expf(v1[j] - m);
        s += __shfl_xor_sync(0xffffffffu, s, 1);
        s += __shfl_xor_sync(0xffffffffu, s, 2);
        float lse = m + logf(s);
        if (r1 < M) {
            #pragma unroll
            for (int j = 0; j < 5; j++)
                *(float2*)(out + (size_t)r1 * 40 + j * 8 + qc * 2) =
                    make_float2(v0[j] - lse, v1[j] - lse);
        }
    }
    // row r2
    {
        float m = -1e30f;
        #pragma unroll
        for (int j = 0; j < 5; j++) m = fmaxf(m, fmaxf(v2[j], v3[j]));
        m = fmaxf(m, __shfl_xor_sync(0xffffffffu, m, 1));
        m = fmaxf(m, __shfl_xor_sync(0xffffffffu, m, 2));
        float s = 0.f;
        #pragma unroll
        for (int j = 0; j < 5; j++) s += expf(v2[j] - m) + expf(v3[j] - m);
        s += __shfl_xor_sync(0xffffffffu, s, 1);
        s += __shfl_xor_sync(0xffffffffu, s, 2);
        float lse = m + logf(s);
        if (r2 < M) {
            #pragma unroll
            for (int j = 0; j < 5; j++)
                *(float2*)(out + (size_t)r2 * 40 + j * 8 + qc * 2) =
                    make_float2(v2[j] - lse, v3[j] - lse);
        }
    }
}

// ---------------- launch ----------------
extern "C" void kernel_launch(void* const* d_in, const int* in_sizes, int n_in,
                              void* d_out, int out_size)
{
    const float* x  = (const float*)d_in[0];
    const int*   ew = (const int*)d_in[1];
    const float* w1 = (const float*)d_in[2];
    const float* b1 = (const float*)d_in[3];
    const float* gw = (const float*)d_in[4];
    const float* gb = (const float*)d_in[5];
    const float* w2 = (const float*)d_in[6];
    const float* b2 = (const float*)d_in[7];
    float* out = (float*)d_out;

    int N = in_sizes[0] / HIDC;
    int E = in_sizes[1] / 2;

    int nb_n = (N + 255) / 256;
    int nb_e2 = (E + 511) / 512;
    int nblk_scan = (N + SCAN_BS - 1) / SCAN_BS;
    int gemm_blocks = (N + 127) / 128;

    const int GEMM_SMEM = 3 * 128 * AST * 4;                    // 202752 B
    const int LIN2_SMEM = (128 * AST + 80 * AST + 40) * 4;      // ~110 KB
    cudaFuncSetAttribute(gemm_tf32, cudaFuncAttributeMaxDynamicSharedMemorySize, GEMM_SMEM);
    cudaFuncSetAttribute(lin2_mma, cudaFuncAttributeMaxDynamicSharedMemorySize, LIN2_SMEM);

    // Launch order puts gemm_tf32 at position 4 (harness ncu captures launch #4).
    detect_k<<<1, 256>>>((const unsigned int*)ew, E);                      // 1
    prep_w_k<<<256, 256>>>(w1, gw);                                        // 2
    zero_cnt_k<<<nb_n, 256>>>(N);                                          // 3
    // lin1: bufA = relu(x @ w1 + b1)   (needs only prep_w)
    gemm_tf32<<<gemm_blocks, 256, GEMM_SMEM>>>(x, 0, 0, b1, 1, 1, 0, 0, N); // 4 <- profiled
    prep_w2_k<<<20, 256>>>(w2);                                            // 5

    count_k<<<nb_e2, 256>>>(ew, E, N);
    scan1_k<<<nblk_scan, SCAN_BS>>>(N);
    scan2_k<<<1, 128>>>(nblk_scan);
    scan3_k<<<nb_n, 256>>>(N);
    fill_k<<<nb_e2, 256>>>(ew, E, N);

    // 3 GCN layers
    for (int k = 0; k < 3; k++) {
        gemm_tf32<<<gemm_blocks, 256, GEMM_SMEM>>>(nullptr, 1, k + 1,
                                                   nullptr, 0, 0, 1, 1, N);
        agg_k<<<(N + 7) / 8, 256>>>(gb + (size_t)k * 128, N);
    }
    // logits + log_softmax (MMA)
    lin2_mma<<<gemm_blocks, 256, LIN2_SMEM>>>(b2, out, N);
}